// round 1
// baseline (speedup 1.0000x reference)
#include <cuda_runtime.h>
#include <cuda_bf16.h>

// Intermediate: h1 after conv1+bn+relu+pool : [8,48,48,48,8] floats = 28.3 MB
__device__ float g_h1[8 * 48 * 48 * 48 * 8];

#define BN_EPS 1e-5f

// ---------------------------------------------------------------------------
// Kernel A: conv1 (3x3x3, 1->8, SAME) + BN(folded) + ReLU + maxpool2
// grid: (216, 8)  [216 = (48/8)^3 tiles, 8 batches], block: 512 = 8x8x8 pooled voxels
// ---------------------------------------------------------------------------
__global__ void __launch_bounds__(512, 1) conv1_pool_kernel(
    const float* __restrict__ x,   // [8,96,96,96,1]
    const float* __restrict__ W1,  // [3,3,3,1,8] -> 216
    const float* __restrict__ b1, const float* __restrict__ g1,
    const float* __restrict__ be1, const float* __restrict__ m1,
    const float* __restrict__ v1)
{
    __shared__ float s_in[18 * 18 * 18];          // input tile (zero-padded)
    __shared__ __align__(16) float s_w[216];      // BN-folded weights
    __shared__ float s_beta[8];                   // BN-folded bias

    const int b  = blockIdx.y;
    const int t  = blockIdx.x;                    // 0..215
    const int td = t / 36, th = (t / 6) % 6, tw = t % 6;
    // pooled tile origin *8 ; conv origin *16 ; input origin = conv-1
    const int I0z = td * 16 - 1, I0y = th * 16 - 1, I0x = tw * 16 - 1;
    const int tid = threadIdx.x;

    // load 18^3 = 5832 input scalars (coalesced along x)
    for (int i = tid; i < 5832; i += 512) {
        int z = i / 324, r = i % 324, y = r / 18, w = r % 18;
        int gz = I0z + z, gy = I0y + y, gx = I0x + w;
        float v = 0.f;
        if ((unsigned)gz < 96u && (unsigned)gy < 96u && (unsigned)gx < 96u)
            v = x[((b * 96 + gz) * 96 + gy) * 96 + gx];
        s_in[i] = v;
    }
    // fold BN into weights: W' = W * g/sqrt(v+eps)
    if (tid < 216) {
        int c = tid & 7;
        float s = g1[c] * rsqrtf(v1[c] + BN_EPS);
        s_w[tid] = W1[tid] * s;
    }
    if (tid < 8) {
        float s = g1[tid] * rsqrtf(v1[tid] + BN_EPS);
        s_beta[tid] = (b1[tid] - m1[tid]) * s + be1[tid];
    }
    __syncthreads();

    const int pw = tid & 7, ph = (tid >> 3) & 7, pd = tid >> 6;
    const int cz = 2 * pd, cy = 2 * ph, cx = 2 * pw;  // conv-local base

    float acc[8][8];   // [pool position][out channel]
    #pragma unroll
    for (int p = 0; p < 8; p++)
        #pragma unroll
        for (int c = 0; c < 8; c++) acc[p][c] = 0.f;

    #pragma unroll 1
    for (int kz = 0; kz < 3; kz++) {
        #pragma unroll 1
        for (int ky = 0; ky < 3; ky++) {
            #pragma unroll
            for (int kx = 0; kx < 3; kx++) {
                const int tap = (kz * 3 + ky) * 3 + kx;
                const float4 wa = *(const float4*)&s_w[tap * 8];
                const float4 wb = *(const float4*)&s_w[tap * 8 + 4];
                #pragma unroll
                for (int p = 0; p < 8; p++) {
                    const int dz = p >> 2, dy = (p >> 1) & 1, dx = p & 1;
                    const float xv =
                        s_in[(cz + dz + kz) * 324 + (cy + dy + ky) * 18 + (cx + dx + kx)];
                    acc[p][0] += xv * wa.x;  acc[p][1] += xv * wa.y;
                    acc[p][2] += xv * wa.z;  acc[p][3] += xv * wa.w;
                    acc[p][4] += xv * wb.x;  acc[p][5] += xv * wb.y;
                    acc[p][6] += xv * wb.z;  acc[p][7] += xv * wb.w;
                }
            }
        }
    }

    // maxpool over 8 positions, add folded bias, relu (commutes with max)
    float outc[8];
    #pragma unroll
    for (int c = 0; c < 8; c++) {
        float m = acc[0][c];
        #pragma unroll
        for (int p = 1; p < 8; p++) m = fmaxf(m, acc[p][c]);
        outc[c] = fmaxf(m + s_beta[c], 0.f);
    }
    float* h1p = &g_h1[(((b * 48 + td * 8 + pd) * 48 + th * 8 + ph) * 48 + tw * 8 + pw) * 8];
    *(float4*)(h1p)     = make_float4(outc[0], outc[1], outc[2], outc[3]);
    *(float4*)(h1p + 4) = make_float4(outc[4], outc[5], outc[6], outc[7]);
}

// ---------------------------------------------------------------------------
// Kernel B: conv2 (3x3x3, 8->16, SAME) + BN(folded) + ReLU + maxpool2 + FC(16->5)
// grid: (216, 8) [216 = (24/4)^3 tiles], block: 64 = 4x4x4 pooled voxels
// ---------------------------------------------------------------------------
__global__ void __launch_bounds__(64, 8) conv2_fc_kernel(
    const float* __restrict__ W2,  // [3,3,3,8,16] -> 3456
    const float* __restrict__ b2, const float* __restrict__ g2,
    const float* __restrict__ be2, const float* __restrict__ m2,
    const float* __restrict__ v2,
    const float* __restrict__ Wf,  // [16,5]
    const float* __restrict__ bf,  // [5]
    float* __restrict__ out)       // [8,24,24,24,5]
{
    __shared__ float s_in[8 * 1000];             // [ci][z][y][x] 10^3 tile, 32 KB
    __shared__ __align__(16) float s_w[3456];    // BN-folded W2, 13.8 KB
    __shared__ float s_scale[16], s_beta[16];
    __shared__ float s_wf[80];
    __shared__ float s_bf[5];

    const int b  = blockIdx.y;
    const int t  = blockIdx.x;
    const int td = t / 36, th = (t / 6) % 6, tw = t % 6;
    const int I0z = td * 8 - 1, I0y = th * 8 - 1, I0x = tw * 8 - 1;
    const int tid = threadIdx.x;

    if (tid < 16) {
        float s = g2[tid] * rsqrtf(v2[tid] + BN_EPS);
        s_scale[tid] = s;
        s_beta[tid]  = (b2[tid] - m2[tid]) * s + be2[tid];
    }
    if (tid < 5) s_bf[tid] = bf[tid];
    for (int i = tid; i < 80; i += 64) s_wf[i] = Wf[i];
    __syncthreads();  // s_scale ready

    // fold BN scale into W2 (co is fastest dim: i & 15)
    for (int i = tid; i < 3456; i += 64)
        s_w[i] = W2[i] * s_scale[i & 15];

    // load 10^3 x 8ch = 8000 floats (linear index = coalesced global reads)
    for (int i = tid; i < 8000; i += 64) {
        int ci = i & 7, vox = i >> 3;
        int z = vox / 100, r = vox % 100, y = r / 10, xw = r % 10;
        int gz = I0z + z, gy = I0y + y, gx = I0x + xw;
        float v = 0.f;
        if ((unsigned)gz < 48u && (unsigned)gy < 48u && (unsigned)gx < 48u)
            v = g_h1[(((b * 48 + gz) * 48 + gy) * 48 + gx) * 8 + ci];
        s_in[ci * 1000 + z * 100 + y * 10 + xw] = v;
    }
    __syncthreads();

    const int pw = tid & 3, ph = (tid >> 2) & 3, pd = tid >> 4;
    const int cz = 2 * pd, cy = 2 * ph, cx = 2 * pw;

    float pool[16];

    #pragma unroll 1
    for (int half = 0; half < 2; half++) {
        float acc[8][8];   // [pool position][co within half]
        #pragma unroll
        for (int p = 0; p < 8; p++)
            #pragma unroll
            for (int c = 0; c < 8; c++) acc[p][c] = 0.f;

        #pragma unroll 1
        for (int kz = 0; kz < 3; kz++) {
            #pragma unroll 1
            for (int ky = 0; ky < 3; ky++) {
                #pragma unroll 1
                for (int kx = 0; kx < 3; kx++) {
                    const int tap = (kz * 3 + ky) * 3 + kx;
                    #pragma unroll
                    for (int ci = 0; ci < 8; ci++) {
                        const float4* wp =
                            (const float4*)&s_w[(tap * 8 + ci) * 16 + half * 8];
                        const float4 wa = wp[0];
                        const float4 wb = wp[1];
                        const float* xin =
                            &s_in[ci * 1000 + (cz + kz) * 100 + (cy + ky) * 10 + (cx + kx)];
                        #pragma unroll
                        for (int p = 0; p < 8; p++) {
                            const int dz = p >> 2, dy = (p >> 1) & 1, dx = p & 1;
                            const float xv = xin[dz * 100 + dy * 10 + dx];
                            acc[p][0] += xv * wa.x;  acc[p][1] += xv * wa.y;
                            acc[p][2] += xv * wa.z;  acc[p][3] += xv * wa.w;
                            acc[p][4] += xv * wb.x;  acc[p][5] += xv * wb.y;
                            acc[p][6] += xv * wb.z;  acc[p][7] += xv * wb.w;
                        }
                    }
                }
            }
        }
        #pragma unroll
        for (int c = 0; c < 8; c++) {
            float m = acc[0][c];
            #pragma unroll
            for (int p = 1; p < 8; p++) m = fmaxf(m, acc[p][c]);
            pool[half * 8 + c] = fmaxf(m + s_beta[half * 8 + c], 0.f);
        }
    }

    // pointwise FC: 16 -> 5
    float* op = &out[(((b * 24 + td * 4 + pd) * 24 + th * 4 + ph) * 24 + tw * 4 + pw) * 5];
    #pragma unroll
    for (int n = 0; n < 5; n++) {
        float o = s_bf[n];
        #pragma unroll
        for (int c = 0; c < 16; c++) o += pool[c] * s_wf[c * 5 + n];
        op[n] = o;
    }
}

// ---------------------------------------------------------------------------
extern "C" void kernel_launch(void* const* d_in, const int* in_sizes, int n_in,
                              void* d_out, int out_size) {
    const float* x   = (const float*)d_in[0];
    const float* W1  = (const float*)d_in[1];
    const float* b1  = (const float*)d_in[2];
    const float* g1  = (const float*)d_in[3];
    const float* be1 = (const float*)d_in[4];
    const float* m1  = (const float*)d_in[5];
    const float* v1  = (const float*)d_in[6];
    const float* W2  = (const float*)d_in[7];
    const float* b2  = (const float*)d_in[8];
    const float* g2  = (const float*)d_in[9];
    const float* be2 = (const float*)d_in[10];
    const float* m2  = (const float*)d_in[11];
    const float* v2  = (const float*)d_in[12];
    const float* Wf  = (const float*)d_in[13];
    const float* bf  = (const float*)d_in[14];
    float* out = (float*)d_out;

    dim3 gridA(216, 8);
    conv1_pool_kernel<<<gridA, 512>>>(x, W1, b1, g1, be1, m1, v1);

    dim3 gridB(216, 8);
    conv2_fc_kernel<<<gridB, 64>>>(W2, b2, g2, be2, m2, v2, Wf, bf, out);
}

// round 2
// speedup vs baseline: 1.2606x; 1.2606x over previous
#include <cuda_runtime.h>
#include <cuda_bf16.h>

// Intermediate: h1 after conv1+bn+relu+pool : [8,48,48,48,8] floats = 28.3 MB
__device__ float g_h1[8 * 48 * 48 * 48 * 8];

#define BN_EPS 1e-5f

// ---- packed fp32x2 helpers (Blackwell double-rate fp32) ---------------------
__device__ __forceinline__ unsigned long long pk2(float a, float b) {
    unsigned long long r;
    asm("mov.b64 %0, {%1, %2};" : "=l"(r) : "f"(a), "f"(b));
    return r;
}
__device__ __forceinline__ void ffma2(unsigned long long& d,
                                      unsigned long long a,
                                      unsigned long long b) {
    asm("fma.rn.f32x2 %0, %1, %2, %0;" : "+l"(d) : "l"(a), "l"(b));
}
__device__ __forceinline__ float2 upk(unsigned long long v) {
    float2 f;
    asm("mov.b64 {%0, %1}, %2;" : "=f"(f.x), "=f"(f.y) : "l"(v));
    return f;
}

// ---------------------------------------------------------------------------
// Kernel A: conv1 (3x3x3, 1->8, SAME) + BN(folded) + ReLU + maxpool2
// grid (216,8), block 512 = 8x8x8 pooled voxels. s_in padded: y-stride 20,
// z-stride 360 (clean 2-way max on the even-offset accesses).
// ---------------------------------------------------------------------------
__global__ void __launch_bounds__(512, 1) conv1_pool_kernel(
    const float* __restrict__ x,   // [8,96,96,96,1]
    const float* __restrict__ W1,  // [3,3,3,1,8] -> 216
    const float* __restrict__ b1, const float* __restrict__ g1,
    const float* __restrict__ be1, const float* __restrict__ m1,
    const float* __restrict__ v1)
{
    __shared__ float s_in[18 * 360];              // [z][y*20][x], 25.9 KB
    __shared__ __align__(16) float s_w[216];      // BN-folded weights [tap][co]
    __shared__ float s_beta[8];

    const int b  = blockIdx.y;
    const int t  = blockIdx.x;                    // 0..215
    const int td = t / 36, th = (t / 6) % 6, tw = t % 6;
    const int I0z = td * 16 - 1, I0y = th * 16 - 1, I0x = tw * 16 - 1;
    const int tid = threadIdx.x;

    // load 18^3 input scalars into padded tile (coalesced along x)
    for (int i = tid; i < 5832; i += 512) {
        int z = i / 324, r = i % 324, y = r / 18, w = r % 18;
        int gz = I0z + z, gy = I0y + y, gx = I0x + w;
        float v = 0.f;
        if ((unsigned)gz < 96u && (unsigned)gy < 96u && (unsigned)gx < 96u)
            v = x[((b * 96 + gz) * 96 + gy) * 96 + gx];
        s_in[z * 360 + y * 20 + w] = v;
    }
    if (tid < 216) {
        int c = tid & 7;
        float s = g1[c] * rsqrtf(v1[c] + BN_EPS);
        s_w[tid] = W1[tid] * s;
    }
    if (tid < 8) {
        float s = g1[tid] * rsqrtf(v1[tid] + BN_EPS);
        s_beta[tid] = (b1[tid] - m1[tid]) * s + be1[tid];
    }
    __syncthreads();

    const int pw = tid & 7, ph = (tid >> 3) & 7, pd = tid >> 6;
    const int cz = 2 * pd, cy = 2 * ph, cx = 2 * pw;

    unsigned long long acc2[8][4];   // [pool pos][co pair], packed f32x2
    #pragma unroll
    for (int p = 0; p < 8; p++)
        #pragma unroll
        for (int c = 0; c < 4; c++) acc2[p][c] = 0ull;

    #pragma unroll 1
    for (int kz = 0; kz < 3; kz++) {
        // register-cache the 2x4x4 input window for this kz
        float xr[2][4][4];
        #pragma unroll
        for (int zz = 0; zz < 2; zz++) {
            const float* rowz = &s_in[(cz + kz + zz) * 360 + cy * 20 + cx];
            #pragma unroll
            for (int yy = 0; yy < 4; yy++) {
                float2 a = *(const float2*)(rowz + yy * 20);
                float2 c = *(const float2*)(rowz + yy * 20 + 2);
                xr[zz][yy][0] = a.x; xr[zz][yy][1] = a.y;
                xr[zz][yy][2] = c.x; xr[zz][yy][3] = c.y;
            }
        }
        #pragma unroll
        for (int ky = 0; ky < 3; ky++) {
            #pragma unroll
            for (int kx = 0; kx < 3; kx++) {
                const int tap = (kz * 3 + ky) * 3 + kx;
                const unsigned long long* wp =
                    (const unsigned long long*)&s_w[tap * 8];
                const unsigned long long w0 = wp[0], w1 = wp[1],
                                         w2 = wp[2], w3 = wp[3];
                #pragma unroll
                for (int p = 0; p < 8; p++) {
                    const int dz = p >> 2, dy = (p >> 1) & 1, dx = p & 1;
                    const float xv = xr[dz][ky + dy][kx + dx];
                    const unsigned long long xx = pk2(xv, xv);
                    ffma2(acc2[p][0], xx, w0);
                    ffma2(acc2[p][1], xx, w1);
                    ffma2(acc2[p][2], xx, w2);
                    ffma2(acc2[p][3], xx, w3);
                }
            }
        }
    }

    // maxpool over 8 positions, folded bias, relu
    float outc[8];
    #pragma unroll
    for (int cp = 0; cp < 4; cp++) {
        float a = -3.4e38f, c = -3.4e38f;
        #pragma unroll
        for (int p = 0; p < 8; p++) {
            float2 f = upk(acc2[p][cp]);
            a = fmaxf(a, f.x);
            c = fmaxf(c, f.y);
        }
        outc[2 * cp]     = fmaxf(a + s_beta[2 * cp], 0.f);
        outc[2 * cp + 1] = fmaxf(c + s_beta[2 * cp + 1], 0.f);
    }
    float* h1p = &g_h1[(((b * 48 + td * 8 + pd) * 48 + th * 8 + ph) * 48 + tw * 8 + pw) * 8];
    *(float4*)(h1p)     = make_float4(outc[0], outc[1], outc[2], outc[3]);
    *(float4*)(h1p + 4) = make_float4(outc[4], outc[5], outc[6], outc[7]);
}

// ---------------------------------------------------------------------------
// Kernel B: conv2 (3x3x3, 8->16, SAME) + BN(folded) + ReLU + maxpool2 + FC(16->5)
// grid (216,8), block 64 = 4x4x4 pooled voxels. s_in padded: y-stride 10,
// z-stride 104, ci-stride 1040.
// ---------------------------------------------------------------------------
__global__ void __launch_bounds__(64, 4) conv2_fc_kernel(
    const float* __restrict__ W2,  // [3,3,3,8,16] -> 3456
    const float* __restrict__ b2, const float* __restrict__ g2,
    const float* __restrict__ be2, const float* __restrict__ m2,
    const float* __restrict__ v2,
    const float* __restrict__ Wf,  // [16,5]
    const float* __restrict__ bf,  // [5]
    float* __restrict__ out)       // [8,24,24,24,5]
{
    __shared__ float s_in[8 * 1040];             // [ci][z*104][y*10][x], 33.3 KB
    __shared__ __align__(16) float s_w[3456];    // BN-folded W2 [tap][ci][co]
    __shared__ float s_scale[16], s_beta[16];
    __shared__ float s_wf[80];
    __shared__ float s_bf[5];

    const int b  = blockIdx.y;
    const int t  = blockIdx.x;
    const int td = t / 36, th = (t / 6) % 6, tw = t % 6;
    const int I0z = td * 8 - 1, I0y = th * 8 - 1, I0x = tw * 8 - 1;
    const int tid = threadIdx.x;

    if (tid < 16) {
        float s = g2[tid] * rsqrtf(v2[tid] + BN_EPS);
        s_scale[tid] = s;
        s_beta[tid]  = (b2[tid] - m2[tid]) * s + be2[tid];
    }
    if (tid < 5) s_bf[tid] = bf[tid];
    for (int i = tid; i < 80; i += 64) s_wf[i] = Wf[i];
    __syncthreads();  // s_scale ready

    for (int i = tid; i < 3456; i += 64)
        s_w[i] = W2[i] * s_scale[i & 15];

    // load 10^3 x 8ch (coalesced global reads; padded smem writes)
    for (int i = tid; i < 8000; i += 64) {
        int ci = i & 7, vox = i >> 3;
        int z = vox / 100, r = vox % 100, y = r / 10, xw = r % 10;
        int gz = I0z + z, gy = I0y + y, gx = I0x + xw;
        float v = 0.f;
        if ((unsigned)gz < 48u && (unsigned)gy < 48u && (unsigned)gx < 48u)
            v = g_h1[(((b * 48 + gz) * 48 + gy) * 48 + gx) * 8 + ci];
        s_in[ci * 1040 + z * 104 + y * 10 + xw] = v;
    }
    __syncthreads();

    const int pw = tid & 3, ph = (tid >> 2) & 3, pd = tid >> 4;
    const int cz = 2 * pd, cy = 2 * ph, cx = 2 * pw;

    float pool[16];

    #pragma unroll 1
    for (int half = 0; half < 2; half++) {
        unsigned long long acc2[8][4];   // [pool pos][co pair within half]
        #pragma unroll
        for (int p = 0; p < 8; p++)
            #pragma unroll
            for (int c = 0; c < 4; c++) acc2[p][c] = 0ull;

        #pragma unroll 1
        for (int kz = 0; kz < 3; kz++) {
            #pragma unroll 1
            for (int ci = 0; ci < 8; ci++) {
                // register-cache the 2x4x4 input window for (kz, ci)
                float xr[2][4][4];
                #pragma unroll
                for (int zz = 0; zz < 2; zz++) {
                    const float* rowz =
                        &s_in[ci * 1040 + (cz + kz + zz) * 104 + cy * 10 + cx];
                    #pragma unroll
                    for (int yy = 0; yy < 4; yy++) {
                        float2 a = *(const float2*)(rowz + yy * 10);
                        float2 c = *(const float2*)(rowz + yy * 10 + 2);
                        xr[zz][yy][0] = a.x; xr[zz][yy][1] = a.y;
                        xr[zz][yy][2] = c.x; xr[zz][yy][3] = c.y;
                    }
                }
                #pragma unroll
                for (int ky = 0; ky < 3; ky++) {
                    #pragma unroll
                    for (int kx = 0; kx < 3; kx++) {
                        const int tap = (kz * 3 + ky) * 3 + kx;
                        const unsigned long long* wp = (const unsigned long long*)
                            &s_w[(tap * 8 + ci) * 16 + half * 8];
                        const unsigned long long w0 = wp[0], w1 = wp[1],
                                                 w2 = wp[2], w3 = wp[3];
                        #pragma unroll
                        for (int p = 0; p < 8; p++) {
                            const int dz = p >> 2, dy = (p >> 1) & 1, dx = p & 1;
                            const float xv = xr[dz][ky + dy][kx + dx];
                            const unsigned long long xx = pk2(xv, xv);
                            ffma2(acc2[p][0], xx, w0);
                            ffma2(acc2[p][1], xx, w1);
                            ffma2(acc2[p][2], xx, w2);
                            ffma2(acc2[p][3], xx, w3);
                        }
                    }
                }
            }
        }
        #pragma unroll
        for (int cp = 0; cp < 4; cp++) {
            float a = -3.4e38f, c = -3.4e38f;
            #pragma unroll
            for (int p = 0; p < 8; p++) {
                float2 f = upk(acc2[p][cp]);
                a = fmaxf(a, f.x);
                c = fmaxf(c, f.y);
            }
            pool[half * 8 + 2 * cp]     = fmaxf(a + s_beta[half * 8 + 2 * cp], 0.f);
            pool[half * 8 + 2 * cp + 1] = fmaxf(c + s_beta[half * 8 + 2 * cp + 1], 0.f);
        }
    }

    // pointwise FC: 16 -> 5
    float* op = &out[(((b * 24 + td * 4 + pd) * 24 + th * 4 + ph) * 24 + tw * 4 + pw) * 5];
    #pragma unroll
    for (int n = 0; n < 5; n++) {
        float o = s_bf[n];
        #pragma unroll
        for (int c = 0; c < 16; c++) o += pool[c] * s_wf[c * 5 + n];
        op[n] = o;
    }
}

// ---------------------------------------------------------------------------
extern "C" void kernel_launch(void* const* d_in, const int* in_sizes, int n_in,
                              void* d_out, int out_size) {
    const float* x   = (const float*)d_in[0];
    const float* W1  = (const float*)d_in[1];
    const float* b1  = (const float*)d_in[2];
    const float* g1  = (const float*)d_in[3];
    const float* be1 = (const float*)d_in[4];
    const float* m1  = (const float*)d_in[5];
    const float* v1  = (const float*)d_in[6];
    const float* W2  = (const float*)d_in[7];
    const float* b2  = (const float*)d_in[8];
    const float* g2  = (const float*)d_in[9];
    const float* be2 = (const float*)d_in[10];
    const float* m2  = (const float*)d_in[11];
    const float* v2  = (const float*)d_in[12];
    const float* Wf  = (const float*)d_in[13];
    const float* bf  = (const float*)d_in[14];
    float* out = (float*)d_out;

    dim3 gridA(216, 8);
    conv1_pool_kernel<<<gridA, 512>>>(x, W1, b1, g1, be1, m1, v1);

    dim3 gridB(216, 8);
    conv2_fc_kernel<<<gridB, 64>>>(W2, b2, g2, be2, m2, v2, Wf, bf, out);
}

// round 3
// speedup vs baseline: 1.3745x; 1.0903x over previous
#include <cuda_runtime.h>
#include <cuda_bf16.h>

// Intermediate: h1 after conv1+bn+relu+pool : [8,48,48,48,8] floats = 28.3 MB
__device__ float g_h1[8 * 48 * 48 * 48 * 8];

#define BN_EPS 1e-5f

// ---- packed fp32x2 helpers (Blackwell double-rate fp32) ---------------------
__device__ __forceinline__ unsigned long long pk2(float a, float b) {
    unsigned long long r;
    asm("mov.b64 %0, {%1, %2};" : "=l"(r) : "f"(a), "f"(b));
    return r;
}
__device__ __forceinline__ void ffma2(unsigned long long& d,
                                      unsigned long long a,
                                      unsigned long long b) {
    asm("fma.rn.f32x2 %0, %1, %2, %0;" : "+l"(d) : "l"(a), "l"(b));
}
__device__ __forceinline__ float2 upk(unsigned long long v) {
    float2 f;
    asm("mov.b64 {%0, %1}, %2;" : "=f"(f.x), "=f"(f.y) : "l"(v));
    return f;
}

// ---------------------------------------------------------------------------
// Kernel A: conv1 (3x3x3, 1->8) + BN(folded) + ReLU + maxpool2
// Pooled tile 8(x) x 4(y) x 4(z); 256 threads = 128 voxels x 2 dz-split.
// smem tile 10z x 10y x 18x, ystride 20, zstride 208 (uniform 2-way LDS.64).
// ---------------------------------------------------------------------------
__global__ void __launch_bounds__(256, 3) conv1_pool_kernel(
    const float* __restrict__ x,   // [8,96,96,96,1]
    const float* __restrict__ W1,  // [3,3,3,1,8] -> 216
    const float* __restrict__ b1, const float* __restrict__ g1,
    const float* __restrict__ be1, const float* __restrict__ m1,
    const float* __restrict__ v1)
{
    __shared__ float s_in[10 * 208];              // 8.3 KB
    __shared__ __align__(16) float s_w[216];      // BN-folded [tap][co]
    __shared__ float s_beta[8];

    const int b  = blockIdx.y;
    const int t  = blockIdx.x;                    // 0..863 = 6(x)*12(y)*12(z)
    const int tw = t % 6, th = (t / 6) % 12, td = t / 72;
    const int I0z = td * 8 - 1, I0y = th * 8 - 1, I0x = tw * 16 - 1;
    const int tid = threadIdx.x;

    // load 10*10*18 = 1800 input scalars
    for (int i = tid; i < 1800; i += 256) {
        int z = i / 180, r = i % 180, y = r / 18, w = r % 18;
        int gz = I0z + z, gy = I0y + y, gx = I0x + w;
        float v = 0.f;
        if ((unsigned)gz < 96u && (unsigned)gy < 96u && (unsigned)gx < 96u)
            v = x[((b * 96 + gz) * 96 + gy) * 96 + gx];
        s_in[z * 208 + y * 20 + w] = v;
    }
    if (tid < 216) {
        int c = tid & 7;
        float s = g1[c] * rsqrtf(v1[c] + BN_EPS);
        s_w[tid] = W1[tid] * s;
    }
    if (tid < 8) {
        float s = g1[tid] * rsqrtf(v1[tid] + BN_EPS);
        s_beta[tid] = (b1[tid] - m1[tid]) * s + be1[tid];
    }
    __syncthreads();

    const int dz = tid & 1;
    const int pw = (tid >> 1) & 7, ph = (tid >> 4) & 3, pd = tid >> 6;
    const int cx = 2 * pw, cy = 2 * ph, cz = 2 * pd;

    unsigned long long acc2[4][4];   // [pos(dy,dx)][co pair]
    #pragma unroll
    for (int p = 0; p < 4; p++)
        #pragma unroll
        for (int c = 0; c < 4; c++) acc2[p][c] = 0ull;

    #pragma unroll 1
    for (int kz = 0; kz < 3; kz++) {
        // cache 4x4 window of slice (cz+dz+kz)
        float xr[4][4];
        const float* sl = &s_in[(cz + dz + kz) * 208 + cy * 20 + cx];
        #pragma unroll
        for (int r = 0; r < 4; r++) {
            float2 a = *(const float2*)(sl + r * 20);
            float2 c = *(const float2*)(sl + r * 20 + 2);
            xr[r][0] = a.x; xr[r][1] = a.y; xr[r][2] = c.x; xr[r][3] = c.y;
        }
        #pragma unroll
        for (int ky = 0; ky < 3; ky++) {
            #pragma unroll
            for (int kx = 0; kx < 3; kx++) {
                const unsigned long long* wp =
                    (const unsigned long long*)&s_w[((kz * 3 + ky) * 3 + kx) * 8];
                const unsigned long long w0 = wp[0], w1 = wp[1],
                                         w2 = wp[2], w3 = wp[3];
                #pragma unroll
                for (int dy = 0; dy < 2; dy++) {
                    #pragma unroll
                    for (int dx = 0; dx < 2; dx++) {
                        const float xv = xr[ky + dy][kx + dx];
                        const unsigned long long xx = pk2(xv, xv);
                        unsigned long long* a = acc2[dy * 2 + dx];
                        ffma2(a[0], xx, w0);
                        ffma2(a[1], xx, w1);
                        ffma2(a[2], xx, w2);
                        ffma2(a[3], xx, w3);
                    }
                }
            }
        }
    }

    // in-thread max over 4 positions, then cross-dz max via shfl
    float mc[8];
    #pragma unroll
    for (int cp = 0; cp < 4; cp++) {
        float2 f0 = upk(acc2[0][cp]);
        float a = f0.x, c = f0.y;
        #pragma unroll
        for (int p = 1; p < 4; p++) {
            float2 f = upk(acc2[p][cp]);
            a = fmaxf(a, f.x); c = fmaxf(c, f.y);
        }
        mc[2 * cp] = a; mc[2 * cp + 1] = c;
    }
    #pragma unroll
    for (int c = 0; c < 8; c++) {
        mc[c] = fmaxf(mc[c], __shfl_xor_sync(0xFFFFFFFFu, mc[c], 1));
        mc[c] = fmaxf(mc[c] + s_beta[c], 0.f);
    }
    // each dz-thread stores one float4 (its half of the channels)
    const int gz = td * 4 + pd, gy = th * 4 + ph, gx = tw * 8 + pw;
    float* h1p = &g_h1[(((b * 48 + gz) * 48 + gy) * 48 + gx) * 8 + 4 * dz];
    *(float4*)h1p = make_float4(mc[4 * dz], mc[4 * dz + 1],
                                mc[4 * dz + 2], mc[4 * dz + 3]);
}

// ---------------------------------------------------------------------------
// Kernel B: conv2 (3x3x3, 8->16) + BN(folded) + ReLU + maxpool2 + FC(16->5)
// 4x4x4 pooled tile; 128 threads = 64 voxels x 2 co-halves.
// ---------------------------------------------------------------------------
__global__ void __launch_bounds__(128, 4) conv2_fc_kernel(
    const float* __restrict__ W2,  // [3,3,3,8,16] -> 3456
    const float* __restrict__ b2, const float* __restrict__ g2,
    const float* __restrict__ be2, const float* __restrict__ m2,
    const float* __restrict__ v2,
    const float* __restrict__ Wf,  // [16,5]
    const float* __restrict__ bf,  // [5]
    float* __restrict__ out)       // [8,24,24,24,5]
{
    __shared__ float s_in[8 * 1040];             // [ci][z*104 + y*10 + x], 33.3 KB
    __shared__ __align__(16) float s_w[3456];    // BN-folded [tap][ci][co]
    __shared__ float s_scale[16], s_beta[16];
    __shared__ float s_wf[80];
    __shared__ float s_bf[5];
    __shared__ float s_part[64][5];              // half-1 FC partials

    const int b  = blockIdx.y;
    const int t  = blockIdx.x;
    const int td = t / 36, th = (t / 6) % 6, tw = t % 6;
    const int I0z = td * 8 - 1, I0y = th * 8 - 1, I0x = tw * 8 - 1;
    const int tid = threadIdx.x;

    if (tid < 16) {
        float s = g2[tid] * rsqrtf(v2[tid] + BN_EPS);
        s_scale[tid] = s;
        s_beta[tid]  = (b2[tid] - m2[tid]) * s + be2[tid];
    }
    if (tid < 5) s_bf[tid] = bf[tid];
    if (tid < 80) s_wf[tid] = Wf[tid];
    __syncthreads();  // s_scale ready

    for (int i = tid; i < 3456; i += 128)
        s_w[i] = W2[i] * s_scale[i & 15];

    for (int i = tid; i < 8000; i += 128) {
        int ci = i & 7, vox = i >> 3;
        int z = vox / 100, r = vox % 100, y = r / 10, xw = r % 10;
        int gz = I0z + z, gy = I0y + y, gx = I0x + xw;
        float v = 0.f;
        if ((unsigned)gz < 48u && (unsigned)gy < 48u && (unsigned)gx < 48u)
            v = g_h1[(((b * 48 + gz) * 48 + gy) * 48 + gx) * 8 + ci];
        s_in[ci * 1040 + z * 104 + y * 10 + xw] = v;
    }
    __syncthreads();

    const int vox  = tid & 63;
    const int half = tid >> 6;                    // warp-uniform
    const int pw = vox & 3, ph = (vox >> 2) & 3, pd = vox >> 4;
    const int cz = 2 * pd, cy = 2 * ph, cx = 2 * pw;

    unsigned long long acc2[8][4];   // [pool pos][co pair within my half]
    #pragma unroll
    for (int p = 0; p < 8; p++)
        #pragma unroll
        for (int c = 0; c < 4; c++) acc2[p][c] = 0ull;

    #pragma unroll 1
    for (int kz = 0; kz < 3; kz++) {
        #pragma unroll 1
        for (int ci = 0; ci < 8; ci++) {
            float xr[2][4][4];
            #pragma unroll
            for (int zz = 0; zz < 2; zz++) {
                const float* rowz =
                    &s_in[ci * 1040 + (cz + kz + zz) * 104 + cy * 10 + cx];
                #pragma unroll
                for (int yy = 0; yy < 4; yy++) {
                    float2 a = *(const float2*)(rowz + yy * 10);
                    float2 c = *(const float2*)(rowz + yy * 10 + 2);
                    xr[zz][yy][0] = a.x; xr[zz][yy][1] = a.y;
                    xr[zz][yy][2] = c.x; xr[zz][yy][3] = c.y;
                }
            }
            #pragma unroll
            for (int ky = 0; ky < 3; ky++) {
                #pragma unroll
                for (int kx = 0; kx < 3; kx++) {
                    const int tap = (kz * 3 + ky) * 3 + kx;
                    const unsigned long long* wp = (const unsigned long long*)
                        &s_w[(tap * 8 + ci) * 16 + half * 8];   // warp-uniform -> broadcast
                    const unsigned long long w0 = wp[0], w1 = wp[1],
                                             w2 = wp[2], w3 = wp[3];
                    #pragma unroll
                    for (int p = 0; p < 8; p++) {
                        const int dzp = p >> 2, dy = (p >> 1) & 1, dx = p & 1;
                        const float xv = xr[dzp][ky + dy][kx + dx];
                        const unsigned long long xx = pk2(xv, xv);
                        ffma2(acc2[p][0], xx, w0);
                        ffma2(acc2[p][1], xx, w1);
                        ffma2(acc2[p][2], xx, w2);
                        ffma2(acc2[p][3], xx, w3);
                    }
                }
            }
        }
    }

    // max over 8 positions + folded bias + relu (my 8 channels)
    float pool[8];
    #pragma unroll
    for (int cp = 0; cp < 4; cp++) {
        float2 f0 = upk(acc2[0][cp]);
        float a = f0.x, c = f0.y;
        #pragma unroll
        for (int p = 1; p < 8; p++) {
            float2 f = upk(acc2[p][cp]);
            a = fmaxf(a, f.x); c = fmaxf(c, f.y);
        }
        pool[2 * cp]     = fmaxf(a + s_beta[half * 8 + 2 * cp], 0.f);
        pool[2 * cp + 1] = fmaxf(c + s_beta[half * 8 + 2 * cp + 1], 0.f);
    }

    // FC partials over my 8 channels
    float o[5];
    #pragma unroll
    for (int n = 0; n < 5; n++) {
        float s = 0.f;
        #pragma unroll
        for (int c = 0; c < 8; c++) s += pool[c] * s_wf[(half * 8 + c) * 5 + n];
        o[n] = s;
    }
    if (half == 1) {
        #pragma unroll
        for (int n = 0; n < 5; n++) s_part[vox][n] = o[n];
    }
    __syncthreads();
    if (half == 0) {
        float* op = &out[(((b * 24 + td * 4 + pd) * 24 + th * 4 + ph) * 24
                          + tw * 4 + pw) * 5];
        #pragma unroll
        for (int n = 0; n < 5; n++) op[n] = o[n] + s_part[vox][n] + s_bf[n];
    }
}

// ---------------------------------------------------------------------------
extern "C" void kernel_launch(void* const* d_in, const int* in_sizes, int n_in,
                              void* d_out, int out_size) {
    const float* x   = (const float*)d_in[0];
    const float* W1  = (const float*)d_in[1];
    const float* b1  = (const float*)d_in[2];
    const float* g1  = (const float*)d_in[3];
    const float* be1 = (const float*)d_in[4];
    const float* m1  = (const float*)d_in[5];
    const float* v1  = (const float*)d_in[6];
    const float* W2  = (const float*)d_in[7];
    const float* b2  = (const float*)d_in[8];
    const float* g2  = (const float*)d_in[9];
    const float* be2 = (const float*)d_in[10];
    const float* m2  = (const float*)d_in[11];
    const float* v2  = (const float*)d_in[12];
    const float* Wf  = (const float*)d_in[13];
    const float* bf  = (const float*)d_in[14];
    float* out = (float*)d_out;

    dim3 gridA(864, 8);   // 6*12*12 tiles
    conv1_pool_kernel<<<gridA, 256>>>(x, W1, b1, g1, be1, m1, v1);

    dim3 gridB(216, 8);
    conv2_fc_kernel<<<gridB, 128>>>(W2, b2, g2, be2, m2, v2, Wf, bf, out);
}

// round 5
// speedup vs baseline: 1.7412x; 1.2668x over previous
#include <cuda_runtime.h>
#include <cuda_bf16.h>
#include <cstdint>

// Intermediate: h1 after conv1+bn+relu+pool : [8,48,48,48,8] floats = 28.3 MB
__device__ float g_h1[8 * 48 * 48 * 48 * 8];

#define BN_EPS 1e-5f

// ---- packed fp32x2 helpers (Blackwell double-rate fp32) ---------------------
__device__ __forceinline__ unsigned long long pk2(float a, float b) {
    unsigned long long r;
    asm("mov.b64 %0, {%1, %2};" : "=l"(r) : "f"(a), "f"(b));
    return r;
}
__device__ __forceinline__ void ffma2(unsigned long long& d,
                                      unsigned long long a,
                                      unsigned long long b) {
    asm("fma.rn.f32x2 %0, %1, %2, %0;" : "+l"(d) : "l"(a), "l"(b));
}
__device__ __forceinline__ float2 upk(unsigned long long v) {
    float2 f;
    asm("mov.b64 {%0, %1}, %2;" : "=f"(f.x), "=f"(f.y) : "l"(v));
    return f;
}

// ---- tf32 mma helpers -------------------------------------------------------
__device__ __forceinline__ uint32_t f2tf32(float f) {
    uint32_t r;
    asm("cvt.rna.tf32.f32 %0, %1;" : "=r"(r) : "f"(f));
    return r;
}
__device__ __forceinline__ void mma_tf32(float* d, const uint32_t* a,
                                         uint32_t b0, uint32_t b1) {
    asm volatile(
        "mma.sync.aligned.m16n8k8.row.col.f32.tf32.tf32.f32 "
        "{%0,%1,%2,%3}, {%4,%5,%6,%7}, {%8,%9}, {%0,%1,%2,%3};"
        : "+f"(d[0]), "+f"(d[1]), "+f"(d[2]), "+f"(d[3])
        : "r"(a[0]), "r"(a[1]), "r"(a[2]), "r"(a[3]), "r"(b0), "r"(b1));
}

// ---------------------------------------------------------------------------
// Kernel A: conv1 (3x3x3, 1->8) + BN(folded) + ReLU + maxpool2  (FFMA2 path)
// ---------------------------------------------------------------------------
__global__ void __launch_bounds__(256, 3) conv1_pool_kernel(
    const float* __restrict__ x,   // [8,96,96,96,1]
    const float* __restrict__ W1,  // [3,3,3,1,8] -> 216
    const float* __restrict__ b1, const float* __restrict__ g1,
    const float* __restrict__ be1, const float* __restrict__ m1,
    const float* __restrict__ v1)
{
    __shared__ float s_in[10 * 208];
    __shared__ __align__(16) float s_w[216];
    __shared__ float s_beta[8];

    const int b  = blockIdx.y;
    const int t  = blockIdx.x;                    // 0..863
    const int tw = t % 6, th = (t / 6) % 12, td = t / 72;
    const int I0z = td * 8 - 1, I0y = th * 8 - 1, I0x = tw * 16 - 1;
    const int tid = threadIdx.x;

    for (int i = tid; i < 1800; i += 256) {
        int z = i / 180, r = i % 180, y = r / 18, w = r % 18;
        int gz = I0z + z, gy = I0y + y, gx = I0x + w;
        float v = 0.f;
        if ((unsigned)gz < 96u && (unsigned)gy < 96u && (unsigned)gx < 96u)
            v = x[((b * 96 + gz) * 96 + gy) * 96 + gx];
        s_in[z * 208 + y * 20 + w] = v;
    }
    if (tid < 216) {
        int c = tid & 7;
        float s = g1[c] * rsqrtf(v1[c] + BN_EPS);
        s_w[tid] = W1[tid] * s;
    }
    if (tid < 8) {
        float s = g1[tid] * rsqrtf(v1[tid] + BN_EPS);
        s_beta[tid] = (b1[tid] - m1[tid]) * s + be1[tid];
    }
    __syncthreads();

    const int dz = tid & 1;
    const int pw = (tid >> 1) & 7, ph = (tid >> 4) & 3, pd = tid >> 6;
    const int cx = 2 * pw, cy = 2 * ph, cz = 2 * pd;

    unsigned long long acc2[4][4];
    #pragma unroll
    for (int p = 0; p < 4; p++)
        #pragma unroll
        for (int c = 0; c < 4; c++) acc2[p][c] = 0ull;

    #pragma unroll 1
    for (int kz = 0; kz < 3; kz++) {
        float xr[4][4];
        const float* sl = &s_in[(cz + dz + kz) * 208 + cy * 20 + cx];
        #pragma unroll
        for (int r = 0; r < 4; r++) {
            float2 a = *(const float2*)(sl + r * 20);
            float2 c = *(const float2*)(sl + r * 20 + 2);
            xr[r][0] = a.x; xr[r][1] = a.y; xr[r][2] = c.x; xr[r][3] = c.y;
        }
        #pragma unroll
        for (int ky = 0; ky < 3; ky++) {
            #pragma unroll
            for (int kx = 0; kx < 3; kx++) {
                const unsigned long long* wp =
                    (const unsigned long long*)&s_w[((kz * 3 + ky) * 3 + kx) * 8];
                const unsigned long long w0 = wp[0], w1 = wp[1],
                                         w2 = wp[2], w3 = wp[3];
                #pragma unroll
                for (int dy = 0; dy < 2; dy++) {
                    #pragma unroll
                    for (int dx = 0; dx < 2; dx++) {
                        const float xv = xr[ky + dy][kx + dx];
                        const unsigned long long xx = pk2(xv, xv);
                        unsigned long long* a = acc2[dy * 2 + dx];
                        ffma2(a[0], xx, w0);
                        ffma2(a[1], xx, w1);
                        ffma2(a[2], xx, w2);
                        ffma2(a[3], xx, w3);
                    }
                }
            }
        }
    }

    float mc[8];
    #pragma unroll
    for (int cp = 0; cp < 4; cp++) {
        float2 f0 = upk(acc2[0][cp]);
        float a = f0.x, c = f0.y;
        #pragma unroll
        for (int p = 1; p < 4; p++) {
            float2 f = upk(acc2[p][cp]);
            a = fmaxf(a, f.x); c = fmaxf(c, f.y);
        }
        mc[2 * cp] = a; mc[2 * cp + 1] = c;
    }
    #pragma unroll
    for (int c = 0; c < 8; c++) {
        mc[c] = fmaxf(mc[c], __shfl_xor_sync(0xFFFFFFFFu, mc[c], 1));
        mc[c] = fmaxf(mc[c] + s_beta[c], 0.f);
    }
    const int gz = td * 4 + pd, gy = th * 4 + ph, gx = tw * 8 + pw;
    float* h1p = &g_h1[(((b * 48 + gz) * 48 + gy) * 48 + gx) * 8 + 4 * dz];
    *(float4*)h1p = make_float4(mc[4 * dz], mc[4 * dz + 1],
                                mc[4 * dz + 2], mc[4 * dz + 3]);
}

// ---------------------------------------------------------------------------
// Kernel B (mma.sync tf32): conv2 + BN + ReLU + maxpool2 + FC
// Block = 128 conv voxels (4z x 4y x 8x), 128 threads, warp w <-> pz = w.
// GEMM: [128 pos] x [K=216] x [16 co] via m16n8k8 tf32 fragments gathered
// straight from the halo tile (immediate-offset LDS, no im2col staging).
// ---------------------------------------------------------------------------
__global__ void __launch_bounds__(128, 6) conv2_mma_kernel(
    const float* __restrict__ W2,  // [3,3,3,8,16] -> [tap][ci][co]
    const float* __restrict__ b2, const float* __restrict__ g2,
    const float* __restrict__ be2, const float* __restrict__ m2,
    const float* __restrict__ v2,
    const float* __restrict__ Wf,  // [16,5]
    const float* __restrict__ bf,  // [5]
    float* __restrict__ out)       // [8,24,24,24,5]
{
    __shared__ float s_in[6 * 6 * 80];           // halo [z][y][x][ci], 11.5 KB (reused as pool buf)
    __shared__ uint32_t s_wB[27 * 128];          // tf32 weights [tap][ci][co], 13.8 KB
    __shared__ float s_wf[80], s_beta[16], s_bf[5];

    const int b  = blockIdx.y;
    const int t  = blockIdx.x;                    // 0..863 = 6(x)*12(y)*12(z)
    const int tx = t % 6, ty = (t / 6) % 12, tz = t / 72;
    const int Z0 = tz * 4, Y0 = ty * 4, X0 = tx * 8;
    const int tid = threadIdx.x;
    const int wid = tid >> 5, lane = tid & 31;

    if (tid < 16) {
        float s = g2[tid] * rsqrtf(v2[tid] + BN_EPS);
        s_beta[tid] = (b2[tid] - m2[tid]) * s + be2[tid];
    }
    if (tid < 80) s_wf[tid] = Wf[tid];
    if (tid < 5)  s_bf[tid] = bf[tid];

    // BN-folded, tf32-rounded weights: s_wB[tap*128 + ci*16 + co]
    for (int i = tid; i < 3456; i += 128) {
        int co = i & 15;
        float s = g2[co] * rsqrtf(v2[co] + BN_EPS);
        s_wB[i] = f2tf32(W2[i] * s);
    }

    // Halo load: [6z][6y][10x][8ci] as float4 pairs (720 float4)
    for (int j = tid; j < 720; j += 128) {
        int cq = j & 1, rest = j >> 1;
        int x10 = rest % 10, yz = rest / 10;
        int y6 = yz % 6, z6 = yz / 6;
        int gz = Z0 - 1 + z6, gy = Y0 - 1 + y6, gx = X0 - 1 + x10;
        float4 v = make_float4(0.f, 0.f, 0.f, 0.f);
        if ((unsigned)gz < 48u && (unsigned)gy < 48u && (unsigned)gx < 48u)
            v = *(const float4*)&g_h1[(((b * 48 + gz) * 48 + gy) * 48 + gx) * 8 + cq * 4];
        *(float4*)&s_in[(z6 * 6 + y6) * 80 + x10 * 8 + cq * 4] = v;
    }
    __syncthreads();

    // fragment thread coords
    const int r_lo = lane >> 2;          // m-row (also n-col for B)
    const int ci_lo = lane & 3;          // k within 8
    const int pz = wid;

    // A base pointers per m-chunk h: position (pz, py=h*2, px=r_lo), channel ci_lo
    const float* aBase0 = &s_in[(pz * 6 + 0) * 80 + r_lo * 8 + ci_lo];
    const float* aBase1 = &s_in[(pz * 6 + 2) * 80 + r_lo * 8 + ci_lo];
    // B base: [tap][ci][co]: b0 at ci_lo, n = r_lo (+nb*8); b1 at ci_lo+4 (+64 words)
    const uint32_t* bBase = &s_wB[ci_lo * 16 + r_lo];

    float d[2][2][4];   // [m-chunk][n-chunk][reg]
    #pragma unroll
    for (int h = 0; h < 2; h++)
        #pragma unroll
        for (int n = 0; n < 2; n++)
            #pragma unroll
            for (int k = 0; k < 4; k++) d[h][n][k] = 0.f;

    #pragma unroll
    for (int tap = 0; tap < 27; tap++) {
        const int dz = tap / 9, dy = (tap / 3) % 3, dx = tap % 3;
        const int aoff = dz * 480 + dy * 80 + dx * 8;
        const uint32_t b00 = bBase[tap * 128];          // nb=0, k lo
        const uint32_t b01 = bBase[tap * 128 + 64];     // nb=0, k hi
        const uint32_t b10 = bBase[tap * 128 + 8];      // nb=1, k lo
        const uint32_t b11 = bBase[tap * 128 + 72];     // nb=1, k hi

        uint32_t a0[4], a1[4];
        a0[0] = f2tf32(aBase0[aoff]);
        a0[1] = f2tf32(aBase0[aoff + 80]);
        a0[2] = f2tf32(aBase0[aoff + 4]);
        a0[3] = f2tf32(aBase0[aoff + 84]);
        a1[0] = f2tf32(aBase1[aoff]);
        a1[1] = f2tf32(aBase1[aoff + 80]);
        a1[2] = f2tf32(aBase1[aoff + 4]);
        a1[3] = f2tf32(aBase1[aoff + 84]);

        mma_tf32(d[0][0], a0, b00, b01);
        mma_tf32(d[0][1], a0, b10, b11);
        mma_tf32(d[1][0], a1, b00, b01);
        mma_tf32(d[1][1], a1, b10, b11);
    }

    __syncthreads();                     // done reading halo; reuse as pool buffer
    float* s_pool = s_in;                // [128 pos][16 co], stride 17
    #pragma unroll
    for (int h = 0; h < 2; h++) {
        const int pos0 = pz * 32 + (h * 2) * 8 + r_lo;       // py = h*2
        const int pos1 = pos0 + 8;                           // py = h*2+1
        #pragma unroll
        for (int nb = 0; nb < 2; nb++) {
            const int co = nb * 8 + 2 * ci_lo;
            s_pool[pos0 * 17 + co]     = d[h][nb][0];
            s_pool[pos0 * 17 + co + 1] = d[h][nb][1];
            s_pool[pos1 * 17 + co]     = d[h][nb][2];
            s_pool[pos1 * 17 + co + 1] = d[h][nb][3];
        }
    }
    __syncthreads();

    // pool(2x2x2) + bias + relu + FC(16->5): 16 pooled voxels (2z x 2y x 4x)
    if (tid < 16) {
        const int qx = tid & 3, qy = (tid >> 2) & 1, qz = tid >> 3;
        float mx[16];
        #pragma unroll
        for (int c = 0; c < 16; c++) mx[c] = -3.4e38f;
        #pragma unroll
        for (int p = 0; p < 8; p++) {
            const int ddz = p >> 2, ddy = (p >> 1) & 1, ddx = p & 1;
            const int m = (2 * qz + ddz) * 32 + (2 * qy + ddy) * 8 + (2 * qx + ddx);
            #pragma unroll
            for (int c = 0; c < 16; c++)
                mx[c] = fmaxf(mx[c], s_pool[m * 17 + c]);
        }
        #pragma unroll
        for (int c = 0; c < 16; c++) mx[c] = fmaxf(mx[c] + s_beta[c], 0.f);
        const int gz = tz * 2 + qz, gy = ty * 2 + qy, gx = tx * 4 + qx;
        float* op = &out[(((b * 24 + gz) * 24 + gy) * 24 + gx) * 5];
        #pragma unroll
        for (int n = 0; n < 5; n++) {
            float o = s_bf[n];
            #pragma unroll
            for (int c = 0; c < 16; c++) o += mx[c] * s_wf[c * 5 + n];
            op[n] = o;
        }
    }
}

// ---------------------------------------------------------------------------
extern "C" void kernel_launch(void* const* d_in, const int* in_sizes, int n_in,
                              void* d_out, int out_size) {
    const float* x   = (const float*)d_in[0];
    const float* W1  = (const float*)d_in[1];
    const float* b1  = (const float*)d_in[2];
    const float* g1  = (const float*)d_in[3];
    const float* be1 = (const float*)d_in[4];
    const float* m1  = (const float*)d_in[5];
    const float* v1  = (const float*)d_in[6];
    const float* W2  = (const float*)d_in[7];
    const float* b2  = (const float*)d_in[8];
    const float* g2  = (const float*)d_in[9];
    const float* be2 = (const float*)d_in[10];
    const float* m2  = (const float*)d_in[11];
    const float* v2  = (const float*)d_in[12];
    const float* Wf  = (const float*)d_in[13];
    const float* bf  = (const float*)d_in[14];
    float* out = (float*)d_out;

    dim3 gridA(864, 8);
    conv1_pool_kernel<<<gridA, 256>>>(x, W1, b1, g1, be1, m1, v1);

    dim3 gridB(864, 8);
    conv2_mma_kernel<<<gridB, 128>>>(W2, b2, g2, be2, m2, v2, Wf, bf, out);
}

// round 7
// speedup vs baseline: 1.8607x; 1.0686x over previous
#include <cuda_runtime.h>
#include <cuda_bf16.h>
#include <cstdint>

// Intermediate: h1 after conv1+bn+relu+pool : [8,48,48,48,8] floats = 28.3 MB
__device__ float g_h1[8 * 48 * 48 * 48 * 8];

#define BN_EPS 1e-5f

// ---- packed fp32x2 helpers (Blackwell double-rate fp32) ---------------------
__device__ __forceinline__ unsigned long long pk2(float a, float b) {
    unsigned long long r;
    asm("mov.b64 %0, {%1, %2};" : "=l"(r) : "f"(a), "f"(b));
    return r;
}
__device__ __forceinline__ void ffma2(unsigned long long& d,
                                      unsigned long long a,
                                      unsigned long long b) {
    asm("fma.rn.f32x2 %0, %1, %2, %0;" : "+l"(d) : "l"(a), "l"(b));
}
__device__ __forceinline__ float2 upk(unsigned long long v) {
    float2 f;
    asm("mov.b64 {%0, %1}, %2;" : "=f"(f.x), "=f"(f.y) : "l"(v));
    return f;
}

// ---- tf32 mma helpers -------------------------------------------------------
__device__ __forceinline__ uint32_t f2tf32(float f) {
    uint32_t r;
    asm("cvt.rna.tf32.f32 %0, %1;" : "=r"(r) : "f"(f));
    return r;
}
__device__ __forceinline__ void mma_tf32_r(float* d, uint32_t a0, uint32_t a1,
                                           uint32_t a2, uint32_t a3,
                                           uint32_t b0, uint32_t b1) {
    asm volatile(
        "mma.sync.aligned.m16n8k8.row.col.f32.tf32.tf32.f32 "
        "{%0,%1,%2,%3}, {%4,%5,%6,%7}, {%8,%9}, {%0,%1,%2,%3};"
        : "+f"(d[0]), "+f"(d[1]), "+f"(d[2]), "+f"(d[3])
        : "r"(a0), "r"(a1), "r"(a2), "r"(a3), "r"(b0), "r"(b1));
}

// ---------------------------------------------------------------------------
// Kernel A: conv1 (3x3x3, 1->8) + BN(folded) + ReLU + maxpool2  (FFMA2 path)
// ---------------------------------------------------------------------------
__global__ void __launch_bounds__(256, 3) conv1_pool_kernel(
    const float* __restrict__ x,   // [8,96,96,96,1]
    const float* __restrict__ W1,  // [3,3,3,1,8] -> 216
    const float* __restrict__ b1, const float* __restrict__ g1,
    const float* __restrict__ be1, const float* __restrict__ m1,
    const float* __restrict__ v1)
{
    __shared__ float s_in[10 * 208];
    __shared__ __align__(16) float s_w[216];
    __shared__ float s_beta[8];

    const int b  = blockIdx.y;
    const int t  = blockIdx.x;                    // 0..863
    const int tw = t % 6, th = (t / 6) % 12, td = t / 72;
    const int I0z = td * 8 - 1, I0y = th * 8 - 1, I0x = tw * 16 - 1;
    const int tid = threadIdx.x;

    for (int i = tid; i < 1800; i += 256) {
        int z = i / 180, r = i % 180, y = r / 18, w = r % 18;
        int gz = I0z + z, gy = I0y + y, gx = I0x + w;
        float v = 0.f;
        if ((unsigned)gz < 96u && (unsigned)gy < 96u && (unsigned)gx < 96u)
            v = x[((b * 96 + gz) * 96 + gy) * 96 + gx];
        s_in[z * 208 + y * 20 + w] = v;
    }
    if (tid < 216) {
        int c = tid & 7;
        float s = g1[c] * rsqrtf(v1[c] + BN_EPS);
        s_w[tid] = W1[tid] * s;
    }
    if (tid < 8) {
        float s = g1[tid] * rsqrtf(v1[tid] + BN_EPS);
        s_beta[tid] = (b1[tid] - m1[tid]) * s + be1[tid];
    }
    __syncthreads();

    const int dz = tid & 1;
    const int pw = (tid >> 1) & 7, ph = (tid >> 4) & 3, pd = tid >> 6;
    const int cx = 2 * pw, cy = 2 * ph, cz = 2 * pd;

    unsigned long long acc2[4][4];
    #pragma unroll
    for (int p = 0; p < 4; p++)
        #pragma unroll
        for (int c = 0; c < 4; c++) acc2[p][c] = 0ull;

    #pragma unroll 1
    for (int kz = 0; kz < 3; kz++) {
        float xr[4][4];
        const float* sl = &s_in[(cz + dz + kz) * 208 + cy * 20 + cx];
        #pragma unroll
        for (int r = 0; r < 4; r++) {
            float2 a = *(const float2*)(sl + r * 20);
            float2 c = *(const float2*)(sl + r * 20 + 2);
            xr[r][0] = a.x; xr[r][1] = a.y; xr[r][2] = c.x; xr[r][3] = c.y;
        }
        #pragma unroll
        for (int ky = 0; ky < 3; ky++) {
            #pragma unroll
            for (int kx = 0; kx < 3; kx++) {
                const unsigned long long* wp =
                    (const unsigned long long*)&s_w[((kz * 3 + ky) * 3 + kx) * 8];
                const unsigned long long w0 = wp[0], w1 = wp[1],
                                         w2 = wp[2], w3 = wp[3];
                #pragma unroll
                for (int dy = 0; dy < 2; dy++) {
                    #pragma unroll
                    for (int dx = 0; dx < 2; dx++) {
                        const float xv = xr[ky + dy][kx + dx];
                        const unsigned long long xx = pk2(xv, xv);
                        unsigned long long* a = acc2[dy * 2 + dx];
                        ffma2(a[0], xx, w0);
                        ffma2(a[1], xx, w1);
                        ffma2(a[2], xx, w2);
                        ffma2(a[3], xx, w3);
                    }
                }
            }
        }
    }

    float mc[8];
    #pragma unroll
    for (int cp = 0; cp < 4; cp++) {
        float2 f0 = upk(acc2[0][cp]);
        float a = f0.x, c = f0.y;
        #pragma unroll
        for (int p = 1; p < 4; p++) {
            float2 f = upk(acc2[p][cp]);
            a = fmaxf(a, f.x); c = fmaxf(c, f.y);
        }
        mc[2 * cp] = a; mc[2 * cp + 1] = c;
    }
    #pragma unroll
    for (int c = 0; c < 8; c++) {
        mc[c] = fmaxf(mc[c], __shfl_xor_sync(0xFFFFFFFFu, mc[c], 1));
        mc[c] = fmaxf(mc[c] + s_beta[c], 0.f);
    }
    const int gz = td * 4 + pd, gy = th * 4 + ph, gx = tw * 8 + pw;
    float* h1p = &g_h1[(((b * 48 + gz) * 48 + gy) * 48 + gx) * 8 + 4 * dz];
    *(float4*)h1p = make_float4(mc[4 * dz], mc[4 * dz + 1],
                                mc[4 * dz + 2], mc[4 * dz + 3]);
}

// ---------------------------------------------------------------------------
// Kernel B (mma.sync tf32, LDS.64 paired): conv2 + BN + ReLU + maxpool2 + FC
// Halo stored pre-converted to tf32, channels interleaved (c0,c4,c1,c5,c2,c6,
// c3,c7) so each A fragment (k, k+4) is one conflict-free LDS.64. Weights
// [tap][co][ci-interleaved] so each B fragment is one LDS.64. No in-loop cvt.
// ---------------------------------------------------------------------------
__global__ void __launch_bounds__(128, 6) conv2_mma_kernel(
    const float* __restrict__ W2,  // [3,3,3,8,16] -> [tap][ci][co]
    const float* __restrict__ b2, const float* __restrict__ g2,
    const float* __restrict__ be2, const float* __restrict__ m2,
    const float* __restrict__ v2,
    const float* __restrict__ Wf,  // [16,5]
    const float* __restrict__ bf,  // [5]
    float* __restrict__ out)       // [8,24,24,24,5]
{
    __shared__ __align__(16) uint32_t s_in[6 * 6 * 80];   // tf32 halo, 11.5 KB (reused as pool buf)
    __shared__ __align__(16) uint32_t s_wB[27 * 128];     // tf32 weights [tap][co][ci-int], 13.8 KB
    __shared__ float s_wf[80], s_beta[16], s_bf[5];

    const int b  = blockIdx.y;
    const int t  = blockIdx.x;                    // 0..863 = 6(x)*12(y)*12(z)
    const int tx = t % 6, ty = (t / 6) % 12, tz = t / 72;
    const int Z0 = tz * 4, Y0 = ty * 4, X0 = tx * 8;
    const int tid = threadIdx.x;
    const int wid = tid >> 5, lane = tid & 31;

    if (tid < 16) {
        float s = g2[tid] * rsqrtf(v2[tid] + BN_EPS);
        s_beta[tid] = (b2[tid] - m2[tid]) * s + be2[tid];
    }
    if (tid < 80) s_wf[tid] = Wf[tid];
    if (tid < 5)  s_bf[tid] = bf[tid];

    // Weights: s_wB[tap*128 + co*8 + slot] ; slot = (ci%4)*2 + ci/4
    for (int i = tid; i < 3456; i += 128) {
        int tap = i >> 7, co = (i >> 3) & 15, slot = i & 7;
        int ci = (slot >> 1) + (slot & 1) * 4;
        float s = g2[co] * rsqrtf(v2[co] + BN_EPS);
        s_wB[i] = f2tf32(W2[tap * 128 + ci * 16 + co] * s);
    }

    // Halo: 360 voxels, each thread handles whole voxel (8 ch), tf32 + interleave
    for (int j = tid; j < 360; j += 128) {
        int x10 = j % 10, yz = j / 10;
        int y6 = yz % 6, z6 = yz / 6;
        int gz = Z0 - 1 + z6, gy = Y0 - 1 + y6, gx = X0 - 1 + x10;
        float4 a = make_float4(0.f, 0.f, 0.f, 0.f), c = a;
        if ((unsigned)gz < 48u && (unsigned)gy < 48u && (unsigned)gx < 48u) {
            const float* p = &g_h1[(((b * 48 + gz) * 48 + gy) * 48 + gx) * 8];
            a = *(const float4*)p;        // c0..c3
            c = *(const float4*)(p + 4);  // c4..c7
        }
        uint32_t* d = &s_in[(z6 * 6 + y6) * 80 + x10 * 8];
        // slots: c0,c4,c1,c5,c2,c6,c3,c7
        ((uint4*)d)[0] = make_uint4(f2tf32(a.x), f2tf32(c.x), f2tf32(a.y), f2tf32(c.y));
        ((uint4*)d)[1] = make_uint4(f2tf32(a.z), f2tf32(c.z), f2tf32(a.w), f2tf32(c.w));
    }
    __syncthreads();

    // fragment thread coords
    const int r_lo = lane >> 2;          // px (m-row) / co (n-col)
    const int ci_lo = lane & 3;          // k within 8
    const int pz = wid;

    // A bases: h selects py pair {2h, 2h+1}
    const uint2* aBase0 = (const uint2*)&s_in[(pz * 6 + 0) * 80 + r_lo * 8 + 2 * ci_lo];
    const uint2* aBase1 = (const uint2*)&s_in[(pz * 6 + 2) * 80 + r_lo * 8 + 2 * ci_lo];
    const uint2* bBase  = (const uint2*)&s_wB[r_lo * 8 + 2 * ci_lo];

    float d[2][2][4];   // [m-chunk h][n-chunk nb][reg]
    #pragma unroll
    for (int h = 0; h < 2; h++)
        #pragma unroll
        for (int n = 0; n < 2; n++)
            #pragma unroll
            for (int k = 0; k < 4; k++) d[h][n][k] = 0.f;

    #pragma unroll
    for (int tap = 0; tap < 27; tap++) {
        const int dz = tap / 9, dy = (tap / 3) % 3, dx = tap % 3;
        const int aoff = (dz * 480 + dy * 80 + dx * 8) >> 1;   // uint2 units
        const uint2 bA = bBase[tap * 64];        // nb=0: (b0, b1)
        const uint2 bB = bBase[tap * 64 + 32];   // nb=1
        // h=0: rows py=0,1 ; h=1: rows py=2,3
        const uint2 l00 = aBase0[aoff];          // (a0, a2) row r
        const uint2 l01 = aBase0[aoff + 40];     // (a1, a3) row r+8 (py+1)
        const uint2 l10 = aBase1[aoff];
        const uint2 l11 = aBase1[aoff + 40];

        mma_tf32_r(d[0][0], l00.x, l01.x, l00.y, l01.y, bA.x, bA.y);
        mma_tf32_r(d[0][1], l00.x, l01.x, l00.y, l01.y, bB.x, bB.y);
        mma_tf32_r(d[1][0], l10.x, l11.x, l10.y, l11.y, bA.x, bA.y);
        mma_tf32_r(d[1][1], l10.x, l11.x, l10.y, l11.y, bB.x, bB.y);
    }

    __syncthreads();                     // done reading halo; reuse as pool buffer
    float* s_pool = (float*)s_in;        // [128 pos][16 co], stride 17
    #pragma unroll
    for (int h = 0; h < 2; h++) {
        const int pos0 = pz * 32 + (h * 2) * 8 + r_lo;       // py = 2h
        const int pos1 = pos0 + 8;                           // py = 2h+1
        #pragma unroll
        for (int nb = 0; nb < 2; nb++) {
            const int co = nb * 8 + 2 * ci_lo;
            s_pool[pos0 * 17 + co]     = d[h][nb][0];
            s_pool[pos0 * 17 + co + 1] = d[h][nb][1];
            s_pool[pos1 * 17 + co]     = d[h][nb][2];
            s_pool[pos1 * 17 + co + 1] = d[h][nb][3];
        }
    }
    __syncthreads();

    // pool(2x2x2) + bias + relu + FC(16->5): 16 pooled voxels (2z x 2y x 4x)
    if (tid < 16) {
        const int qx = tid & 3, qy = (tid >> 2) & 1, qz = tid >> 3;
        float mx[16];
        #pragma unroll
        for (int c = 0; c < 16; c++) mx[c] = -3.4e38f;
        #pragma unroll
        for (int p = 0; p < 8; p++) {
            const int ddz = p >> 2, ddy = (p >> 1) & 1, ddx = p & 1;
            const int m = (2 * qz + ddz) * 32 + (2 * qy + ddy) * 8 + (2 * qx + ddx);
            #pragma unroll
            for (int c = 0; c < 16; c++)
                mx[c] = fmaxf(mx[c], s_pool[m * 17 + c]);
        }
        #pragma unroll
        for (int c = 0; c < 16; c++) mx[c] = fmaxf(mx[c] + s_beta[c], 0.f);
        const int gz = tz * 2 + qz, gy = ty * 2 + qy, gx = tx * 4 + qx;
        float* op = &out[(((b * 24 + gz) * 24 + gy) * 24 + gx) * 5];
        #pragma unroll
        for (int n = 0; n < 5; n++) {
            float o = s_bf[n];
            #pragma unroll
            for (int c = 0; c < 16; c++) o += mx[c] * s_wf[c * 5 + n];
            op[n] = o;
        }
    }
}

// ---------------------------------------------------------------------------
extern "C" void kernel_launch(void* const* d_in, const int* in_sizes, int n_in,
                              void* d_out, int out_size) {
    const float* x   = (const float*)d_in[0];
    const float* W1  = (const float*)d_in[1];
    const float* b1  = (const float*)d_in[2];
    const float* g1  = (const float*)d_in[3];
    const float* be1 = (const float*)d_in[4];
    const float* m1  = (const float*)d_in[5];
    const float* v1  = (const float*)d_in[6];
    const float* W2  = (const float*)d_in[7];
    const float* b2  = (const float*)d_in[8];
    const float* g2  = (const float*)d_in[9];
    const float* be2 = (const float*)d_in[10];
    const float* m2  = (const float*)d_in[11];
    const float* v2  = (const float*)d_in[12];
    const float* Wf  = (const float*)d_in[13];
    const float* bf  = (const float*)d_in[14];
    float* out = (float*)d_out;

    dim3 gridA(864, 8);
    conv1_pool_kernel<<<gridA, 256>>>(x, W1, b1, g1, be1, m1, v1);

    dim3 gridB(864, 8);
    conv2_mma_kernel<<<gridB, 128>>>(W2, b2, g2, be2, m2, v2, Wf, bf, out);
}